// round 6
// baseline (speedup 1.0000x reference)
#include <cuda_runtime.h>
#include <math.h>

#define Bn 8
#define Nn 192
#define Dn 768
#define Hn 150
#define HSP 152  // Hs row stride (floats)

// ---- packed fp32x2 helpers (Blackwell FFMA2 path) ----
typedef unsigned long long ull;
__device__ __forceinline__ ull pack2(float x, float y) {
    ull r; asm("mov.b64 %0, {%1, %2};" : "=l"(r) : "f"(x), "f"(y)); return r;
}
__device__ __forceinline__ void unpack2(ull v, float& x, float& y) {
    asm("mov.b64 {%0, %1}, %2;" : "=f"(x), "=f"(y) : "l"(v));
}
__device__ __forceinline__ ull fma2(ull a, ull b, ull c) {
    ull d; asm("fma.rn.f32x2 %0, %1, %2, %3;" : "=l"(d) : "l"(a), "l"(b), "l"(c)); return d;
}

// Scratch: per-token projections A = E@W1a + b1, Bm = E@W1b
__device__ float g_A[Bn * Nn * Hn];
__device__ float g_Bm[Bn * Nn * Hn];

// ---------------------------------------------------------------------------
// Kernel 1: per-token projections. Block: 16 rows x 160 h. blockIdx.y: 0->A, 1->Bm
// ---------------------------------------------------------------------------
__global__ void precompute_kernel(const float* __restrict__ E,
                                  const float* __restrict__ W1,
                                  const float* __restrict__ b1) {
    __shared__ float Es[16][32];
    __shared__ float Ws[32][160];
    const int hg = threadIdx.x;       // 0..15
    const int rg = threadIdx.y;       // 0..15
    const int tid = rg * 16 + hg;
    const int row0 = blockIdx.x * 16; // 96 blocks cover 1536 rows
    const float* W = W1 + (size_t)blockIdx.y * Dn * Hn; // W1a or W1b
    float* out = blockIdx.y ? g_Bm : g_A;

    float acc[10];
#pragma unroll
    for (int t = 0; t < 10; t++) acc[t] = 0.f;

    for (int kc = 0; kc < Dn; kc += 32) {
        {
            int l = tid;
            Es[l >> 5][l & 31] = E[(size_t)(row0 + (l >> 5)) * Dn + kc + (l & 31)];
            l += 256;
            Es[l >> 5][l & 31] = E[(size_t)(row0 + (l >> 5)) * Dn + kc + (l & 31)];
        }
        for (int l = tid; l < 32 * 160; l += 256) {
            int k = l / 160, h = l % 160;
            Ws[k][h] = (h < Hn) ? W[(size_t)(kc + k) * Hn + h] : 0.f;
        }
        __syncthreads();
#pragma unroll 8
        for (int k = 0; k < 32; k++) {
            float e = Es[rg][k];
#pragma unroll
            for (int t = 0; t < 10; t++) acc[t] += e * Ws[k][hg + 16 * t];
        }
        __syncthreads();
    }

    const int row = row0 + rg;
#pragma unroll
    for (int t = 0; t < 10; t++) {
        int h = hg + 16 * t;
        if (h < Hn) {
            float v = acc[t];
            if (blockIdx.y == 0) v += b1[h];
            out[(size_t)row * Hn + h] = v;
        }
    }
}

// ---------------------------------------------------------------------------
// Kernel 2: fused pair MLP, FFMA2-packed.
// Block = 8x8 (i,j) tile = 64 pairs. x=hg(16) h-strided, y=pg(16) -> 4 pairs.
// Per thread: pairs share i (il), j = jlb..jlb+3; h set = hg+16*hh, hh=0..9,
// packed as (hh=2t, hh=2t+1) i.e. h = hg+32t and hg+32t+16.
// ---------------------------------------------------------------------------
__global__ __launch_bounds__(256) void pair_kernel(
    const float* __restrict__ E, const float* __restrict__ W1,
    const float* __restrict__ W2, const float* __restrict__ b2,
    const float* __restrict__ W3, const float* __restrict__ b3,
    float* __restrict__ out) {
    extern __shared__ float sm[];
    float*  Ei  = sm;                          // 8 x 33          (264 f)
    float*  Ejs = sm + 264;                    // 32 x 8 [k][j]   (256 f)
    float2* Wp  = (float2*)(sm + 520);         // [k][hg][t] 32*16*5 float2 (5120 f)
    float*  Hs  = sm + 520 + 5120;             // 64 x HSP        (9728 f)

    const int hg = threadIdx.x;
    const int pg = threadIdx.y;
    const int tid = pg * 16 + hg;
    const int t = blockIdx.x;  // triangular tile index
    const int b = blockIdx.y;

    // decode (bi, bj), bj <= bi, t = bi*(bi+1)/2 + bj
    int bi = (int)((sqrtf(8.f * (float)t + 1.f) - 1.f) * 0.5f);
    while ((bi + 1) * (bi + 2) / 2 <= t) bi++;
    while (bi * (bi + 1) / 2 > t) bi--;
    const int bj = t - bi * (bi + 1) / 2;
    const int i0 = bi * 8, j0 = bj * 8;

    const int il = pg >> 1;           // this thread's pairs share i
    const int jlb = (pg & 1) * 4;     // j local base

    ull accp[4][5];
#pragma unroll
    for (int q = 0; q < 4; q++)
#pragma unroll
        for (int tt = 0; tt < 5; tt++) accp[q][tt] = 0ULL;

    const float* Wc = W1 + (size_t)2 * Dn * Hn; // W1c (product block)
    const float* Ebase = E + (size_t)b * Nn * Dn;

    // ---- Layer 1 (product-term GEMM) ----
    for (int kc = 0; kc < Dn; kc += 32) {
        {
            int r = tid >> 5, k = tid & 31;
            Ei[r * 33 + k] = Ebase[(size_t)(i0 + r) * Dn + kc + k];
            Ejs[k * 8 + r] = Ebase[(size_t)(j0 + r) * Dn + kc + k];
        }
        // pack W1c tile: Wp[k][hg][t] = (W[h], W[h+16]), h = hg+32t
        for (int l = tid; l < 32 * 160; l += 256) {
            int k = l / 160, h = l % 160;
            float w = (h < Hn) ? Wc[(size_t)(kc + k) * Hn + h] : 0.f;
            int hgl = h & 15, m = h >> 4;          // m = 0..9
            int tt = m >> 1, half = m & 1;
            ((float*)Wp)[(((k * 16 + hgl) * 5 + tt) << 1) | half] = w;
        }
        __syncthreads();
#pragma unroll 4
        for (int k = 0; k < 32; k++) {
            const float ei = Ei[il * 33 + k];
            const float4 ej4 = *reinterpret_cast<const float4*>(&Ejs[k * 8 + jlb]);
            ull vd[4];
            vd[0] = pack2(ei * ej4.x, ei * ej4.x);
            vd[1] = pack2(ei * ej4.y, ei * ej4.y);
            vd[2] = pack2(ei * ej4.z, ei * ej4.z);
            vd[3] = pack2(ei * ej4.w, ei * ej4.w);
            const float2* wrow = Wp + (k * 16 + hg) * 5;
#pragma unroll
            for (int tt = 0; tt < 5; tt++) {
                float2 wv = wrow[tt];
                ull w2 = pack2(wv.x, wv.y);
#pragma unroll
                for (int q = 0; q < 4; q++) accp[q][tt] = fma2(vd[q], w2, accp[q][tt]);
            }
        }
        __syncthreads();
    }

    // ---- Layer-1 epilogue: add per-token terms, ReLU, stash to smem ----
#pragma unroll
    for (int q = 0; q < 4; q++) {
        const int i = i0 + il, j = j0 + jlb + q;
        const float* Ar = g_A + (size_t)(b * Nn + i) * Hn;
        const float* Br = g_Bm + (size_t)(b * Nn + j) * Hn;
        const int p = pg * 4 + q;
#pragma unroll
        for (int tt = 0; tt < 5; tt++) {
            float lo, hi;
            unpack2(accp[q][tt], lo, hi);
            int h0 = hg + 32 * tt;       // always < 150
            int h1 = h0 + 16;
            Hs[p * HSP + h0] = fmaxf(lo + Ar[h0] + Br[h0], 0.f);
            if (h1 < Hn)
                Hs[p * HSP + h1] = fmaxf(hi + Ar[h1] + Br[h1], 0.f);
        }
    }
    __syncthreads();

    // ---- Layer 2 (packed) ----
    ull acc2p[4][5];
#pragma unroll
    for (int q = 0; q < 4; q++)
#pragma unroll
        for (int tt = 0; tt < 5; tt++) acc2p[q][tt] = 0ULL;

    for (int kc = 0; kc < Hn; kc += 30) {
        for (int l = tid; l < 30 * 160; l += 256) {
            int k = l / 160, h = l % 160;
            float w = (h < Hn) ? W2[(size_t)(kc + k) * Hn + h] : 0.f;
            int hgl = h & 15, m = h >> 4;
            int tt = m >> 1, half = m & 1;
            ((float*)Wp)[(((k * 16 + hgl) * 5 + tt) << 1) | half] = w;
        }
        __syncthreads();
#pragma unroll 2
        for (int k = 0; k < 30; k++) {
            ull hd[4];
#pragma unroll
            for (int q = 0; q < 4; q++) {
                float hv = Hs[(pg * 4 + q) * HSP + kc + k];
                hd[q] = pack2(hv, hv);
            }
            const float2* wrow = Wp + (k * 16 + hg) * 5;
#pragma unroll
            for (int tt = 0; tt < 5; tt++) {
                float2 wv = wrow[tt];
                ull w2 = pack2(wv.x, wv.y);
#pragma unroll
                for (int q = 0; q < 4; q++) acc2p[q][tt] = fma2(hd[q], w2, acc2p[q][tt]);
            }
        }
        __syncthreads();
    }

    // ---- Layer 3 + reduction + scatter ----
    float part[4];
#pragma unroll
    for (int q = 0; q < 4; q++) {
        float s = 0.f;
#pragma unroll
        for (int tt = 0; tt < 5; tt++) {
            float lo, hi;
            unpack2(acc2p[q][tt], lo, hi);
            int h0 = hg + 32 * tt;
            int h1 = h0 + 16;
            s += fmaxf(lo + b2[h0], 0.f) * W3[h0];
            if (h1 < Hn) s += fmaxf(hi + b2[h1], 0.f) * W3[h1];
        }
        part[q] = s;
    }
#pragma unroll
    for (int off = 8; off; off >>= 1) {
#pragma unroll
        for (int q = 0; q < 4; q++)
            part[q] += __shfl_down_sync(0xffffffffu, part[q], off, 16);
    }
    if (hg == 0) {
        const float bias3 = b3[0];
        const int i = i0 + il;
#pragma unroll
        for (int q = 0; q < 4; q++) {
            const int j = j0 + jlb + q;
            if (i > j)
                out[((size_t)(b * Nn + i)) * Nn + j] = part[q] + bias3;
        }
    }
}

// ---------------------------------------------------------------------------
// Kernel 3: per-row masked softmax (in-place on out), fills upper tri w/ -1000
// ---------------------------------------------------------------------------
__global__ void softmax_kernel(float* __restrict__ out) {
    __shared__ float red[8];
    const int row = blockIdx.x;       // b*N + i
    const int i = row % Nn;
    const int tid = threadIdx.x;      // 0..191
    float* r = out + (size_t)row * Nn;

    float x = (tid < i) ? r[tid] : (tid == i ? 0.f : -INFINITY);

    // block max
    float m = x;
#pragma unroll
    for (int off = 16; off; off >>= 1)
        m = fmaxf(m, __shfl_xor_sync(0xffffffffu, m, off));
    if ((tid & 31) == 0) red[tid >> 5] = m;
    __syncthreads();
    if (tid < 8) {
        float mm = (tid < 6) ? red[tid] : -INFINITY;
#pragma unroll
        for (int off = 4; off; off >>= 1)
            mm = fmaxf(mm, __shfl_xor_sync(0xffu, mm, off));
        if (tid == 0) red[0] = mm;
    }
    __syncthreads();
    const float bm = red[0];
    __syncthreads();

    float e = (tid <= i) ? __expf(x - bm) : 0.f;
    float s = e;
#pragma unroll
    for (int off = 16; off; off >>= 1)
        s += __shfl_xor_sync(0xffffffffu, s, off);
    if ((tid & 31) == 0) red[tid >> 5] = s;
    __syncthreads();
    if (tid < 8) {
        float ss = (tid < 6) ? red[tid] : 0.f;
#pragma unroll
        for (int off = 4; off; off >>= 1)
            ss += __shfl_xor_sync(0xffu, ss, off);
        if (tid == 0) red[0] = ss;
    }
    __syncthreads();
    const float invZ = 1.f / red[0];

    r[tid] = (tid <= i) ? e * invZ : -1000.0f;
}

// ---------------------------------------------------------------------------
extern "C" void kernel_launch(void* const* d_in, const int* in_sizes, int n_in,
                              void* d_out, int out_size) {
    const float* E  = (const float*)d_in[0];
    const float* W1 = (const float*)d_in[1];
    const float* b1 = (const float*)d_in[2];
    const float* W2 = (const float*)d_in[3];
    const float* b2 = (const float*)d_in[4];
    const float* W3 = (const float*)d_in[5];
    const float* b3 = (const float*)d_in[6];
    float* out = (float*)d_out;

    // dynamic smem for pair_kernel: Ei(264) + Ejs(256) + Wp(5120) + Hs(64*152)
    const int smem_bytes = (264 + 256 + 5120 + 64 * HSP) * (int)sizeof(float);
    cudaFuncSetAttribute(pair_kernel,
                         cudaFuncAttributeMaxDynamicSharedMemorySize, smem_bytes);

    dim3 blk(16, 16);
    precompute_kernel<<<dim3(Bn * Nn / 16, 2), blk>>>(E, W1, b1);

    const int n_tiles = (Nn / 8) * (Nn / 8 + 1) / 2; // 300
    pair_kernel<<<dim3(n_tiles, Bn), blk, smem_bytes>>>(E, W1, W2, b2, W3, b3, out);

    softmax_kernel<<<Bn * Nn, Nn>>>(out);
}

// round 8
// speedup vs baseline: 1.0081x; 1.0081x over previous
#include <cuda_runtime.h>
#include <math.h>

#define Bn 8
#define Nn 192
#define Dn 768
#define Hn 150
#define HSB 150   // Hs row stride (floats)
#define PSTR 66   // Ps2 row stride (ull), 528B: 16B-aligned rows

// ---- packed fp32x2 helpers (Blackwell FFMA2 path) ----
typedef unsigned long long ull;
__device__ __forceinline__ ull pack2(float x, float y) {
    ull r; asm("mov.b64 %0, {%1, %2};" : "=l"(r) : "f"(x), "f"(y)); return r;
}
__device__ __forceinline__ void unpack2(ull v, float& x, float& y) {
    asm("mov.b64 {%0, %1}, %2;" : "=f"(x), "=f"(y) : "l"(v));
}
__device__ __forceinline__ ull fma2(ull a, ull b, ull c) {
    ull d; asm("fma.rn.f32x2 %0, %1, %2, %3;" : "=l"(d) : "l"(a), "l"(b), "l"(c)); return d;
}

// Scratch: per-token projections A = E@W1a + b1, Bm = E@W1b
__device__ float g_A[Bn * Nn * Hn];
__device__ float g_Bm[Bn * Nn * Hn];

// ---------------------------------------------------------------------------
// Kernel 1: per-token projections. Grid (96 rowtiles, 5 htiles, 2 mats),
// block 16x16. Each block: 16 rows x 32 h. 960 blocks -> ~6.5/SM.
// ---------------------------------------------------------------------------
__global__ void precompute_kernel(const float* __restrict__ E,
                                  const float* __restrict__ W1,
                                  const float* __restrict__ b1) {
    __shared__ float Es[16][33];
    __shared__ float Ws[32][33];
    const int hg = threadIdx.x;        // 0..15
    const int rg = threadIdx.y;        // 0..15
    const int tid = rg * 16 + hg;
    const int row0 = blockIdx.x * 16;  // 96 row tiles
    const int h0 = blockIdx.y * 32;    // 5 h tiles
    const int mat = blockIdx.z;        // 0 -> A, 1 -> Bm
    const float* W = W1 + (size_t)mat * Dn * Hn;
    float* out = mat ? g_Bm : g_A;

    float acc0 = 0.f, acc1 = 0.f;

    for (int kc = 0; kc < Dn; kc += 32) {
        {
            int l = tid;
            Es[l >> 5][l & 31] = E[(size_t)(row0 + (l >> 5)) * Dn + kc + (l & 31)];
            l += 256;
            Es[l >> 5][l & 31] = E[(size_t)(row0 + (l >> 5)) * Dn + kc + (l & 31)];
        }
#pragma unroll
        for (int e = 0; e < 4; e++) {
            int l = e * 256 + tid;
            int k = l >> 5, hl = l & 31;
            int h = h0 + hl;
            Ws[k][hl] = (h < Hn) ? W[(size_t)(kc + k) * Hn + h] : 0.f;
        }
        __syncthreads();
#pragma unroll 8
        for (int k = 0; k < 32; k++) {
            float e = Es[rg][k];
            acc0 += e * Ws[k][hg];
            acc1 += e * Ws[k][hg + 16];
        }
        __syncthreads();
    }

    const int row = row0 + rg;
    const int ha = h0 + hg, hb = ha + 16;
    if (ha < Hn) out[(size_t)row * Hn + ha] = acc0 + (mat ? 0.f : b1[ha]);
    if (hb < Hn) out[(size_t)row * Hn + hb] = acc1 + (mat ? 0.f : b1[hb]);
}

// ---------------------------------------------------------------------------
// Kernel 2: fused pair MLP, high-purity FFMA2.
// Block = 8x8 (i,j) tile = 64 pairs. x=hg(16), y=pg(16) -> 4 pairs each.
// Pair products P[k][p] prebuilt duplicated (v,v) in smem; W tiles prepacked
// as (W[h], W[h+16]) 8B words -> inner loop is LDS.128/LDS.64 + FFMA2 only.
// ---------------------------------------------------------------------------
__global__ __launch_bounds__(256) void pair_kernel(
    const float* __restrict__ E, const float* __restrict__ W1,
    const float* __restrict__ W2, const float* __restrict__ b2,
    const float* __restrict__ W3, const float* __restrict__ b3,
    float* __restrict__ out) {
    extern __shared__ float sm[];
    ull*   Wd  = (ull*)sm;                    // 32*16*5 ull      (5120 f)
    ull*   Ps2 = (ull*)(sm + 5120);           // 32 x PSTR ull    (4224 f)
    float* Hs  = sm + 5120 + 4224;            // 64 x HSB         (9600 f)

    const int hg = threadIdx.x;
    const int pg = threadIdx.y;
    const int tid = pg * 16 + hg;
    const int t = blockIdx.x;  // triangular tile index
    const int b = blockIdx.y;

    // decode (bi, bj), bj <= bi, t = bi*(bi+1)/2 + bj
    int bi = (int)((sqrtf(8.f * (float)t + 1.f) - 1.f) * 0.5f);
    while ((bi + 1) * (bi + 2) / 2 <= t) bi++;
    while (bi * (bi + 1) / 2 > t) bi--;
    const int bj = t - bi * (bi + 1) / 2;
    const int i0 = bi * 8, j0 = bj * 8;

    const int il = pg >> 1;           // this thread's pairs share i
    const int jlb = (pg & 1) * 4;     // j local base
    const int p0 = pg * 4;            // == il*8 + jlb

    ull accp[4][5];
#pragma unroll
    for (int q = 0; q < 4; q++)
#pragma unroll
        for (int tt = 0; tt < 5; tt++) accp[q][tt] = 0ULL;

    const float* Wc = W1 + (size_t)2 * Dn * Hn; // W1c (product block)
    const float* Ebase = E + (size_t)b * Nn * Dn;

    // ---- Layer 1 (product-term GEMM) ----
    for (int kc = 0; kc < Dn; kc += 32) {
        // build duplicated pair products: Ps2[k][p] = (ei*ej, ei*ej)
#pragma unroll
        for (int e = 0; e < 8; e++) {
            int idx = e * 256 + tid;        // warp: p fixed, k = lane
            int k = idx & 31;
            int p = idx >> 5;
            float vi = Ebase[(size_t)(i0 + (p >> 3)) * Dn + kc + k];
            float vj = Ebase[(size_t)(j0 + (p & 7)) * Dn + kc + k];
            float v = vi * vj;
            Ps2[k * PSTR + p] = pack2(v, v);
        }
        // pack W1c tile: Wd[(k*16+hg)*5+tt] = (W[hg+32tt], W[hg+32tt+16])
        for (int l = tid; l < 32 * 160; l += 256) {
            int k = l / 160, h = l % 160;
            float w = (h < Hn) ? Wc[(size_t)(kc + k) * Hn + h] : 0.f;
            int hgl = h & 15, m = h >> 4;   // m = 0..9
            int tt = m >> 1, half = m & 1;
            ((float*)Wd)[(((k * 16 + hgl) * 5 + tt) << 1) | half] = w;
        }
        __syncthreads();
#pragma unroll 4
        for (int k = 0; k < 32; k++) {
            const ull* prow = Ps2 + k * PSTR + p0;
            ulonglong2 va = *reinterpret_cast<const ulonglong2*>(prow);
            ulonglong2 vb = *reinterpret_cast<const ulonglong2*>(prow + 2);
            const ull* wrow = Wd + (k * 16 + hg) * 5;
#pragma unroll
            for (int tt = 0; tt < 5; tt++) {
                ull w2 = wrow[tt];
                accp[0][tt] = fma2(va.x, w2, accp[0][tt]);
                accp[1][tt] = fma2(va.y, w2, accp[1][tt]);
                accp[2][tt] = fma2(vb.x, w2, accp[2][tt]);
                accp[3][tt] = fma2(vb.y, w2, accp[3][tt]);
            }
        }
        __syncthreads();
    }

    // ---- Layer-1 epilogue: add per-token terms, ReLU, stash to smem ----
#pragma unroll
    for (int q = 0; q < 4; q++) {
        const int i = i0 + il, j = j0 + jlb + q;
        const float* Ar = g_A + (size_t)(b * Nn + i) * Hn;
        const float* Br = g_Bm + (size_t)(b * Nn + j) * Hn;
        const int p = p0 + q;
#pragma unroll
        for (int tt = 0; tt < 5; tt++) {
            float lo, hi;
            unpack2(accp[q][tt], lo, hi);
            int h0 = hg + 32 * tt;       // always < 150
            int h1 = h0 + 16;
            Hs[p * HSB + h0] = fmaxf(lo + Ar[h0] + Br[h0], 0.f);
            if (h1 < Hn)
                Hs[p * HSB + h1] = fmaxf(hi + Ar[h1] + Br[h1], 0.f);
        }
    }
    __syncthreads();

    // ---- Layer 2 (packed, direct-w) ----
    ull acc2p[4][5];
#pragma unroll
    for (int q = 0; q < 4; q++)
#pragma unroll
        for (int tt = 0; tt < 5; tt++) acc2p[q][tt] = 0ULL;

    for (int kc = 0; kc < Hn; kc += 30) {
        for (int l = tid; l < 30 * 160; l += 256) {
            int k = l / 160, h = l % 160;
            float w = (h < Hn) ? W2[(size_t)(kc + k) * Hn + h] : 0.f;
            int hgl = h & 15, m = h >> 4;
            int tt = m >> 1, half = m & 1;
            ((float*)Wd)[(((k * 16 + hgl) * 5 + tt) << 1) | half] = w;
        }
        __syncthreads();
#pragma unroll 2
        for (int k = 0; k < 30; k++) {
            ull hd[4];
#pragma unroll
            for (int q = 0; q < 4; q++) {
                float hv = Hs[(p0 + q) * HSB + kc + k];
                hd[q] = pack2(hv, hv);
            }
            const ull* wrow = Wd + (k * 16 + hg) * 5;
#pragma unroll
            for (int tt = 0; tt < 5; tt++) {
                ull w2 = wrow[tt];
#pragma unroll
                for (int q = 0; q < 4; q++) acc2p[q][tt] = fma2(hd[q], w2, acc2p[q][tt]);
            }
        }
        __syncthreads();
    }

    // ---- Layer 3 + reduction + scatter ----
    float part[4];
#pragma unroll
    for (int q = 0; q < 4; q++) {
        float s = 0.f;
#pragma unroll
        for (int tt = 0; tt < 5; tt++) {
            float lo, hi;
            unpack2(acc2p[q][tt], lo, hi);
            int h0 = hg + 32 * tt;
            int h1 = h0 + 16;
            s += fmaxf(lo + b2[h0], 0.f) * W3[h0];
            if (h1 < Hn) s += fmaxf(hi + b2[h1], 0.f) * W3[h1];
        }
        part[q] = s;
    }
#pragma unroll
    for (int off = 8; off; off >>= 1) {
#pragma unroll
        for (int q = 0; q < 4; q++)
            part[q] += __shfl_down_sync(0xffffffffu, part[q], off, 16);
    }
    if (hg == 0) {
        const float bias3 = b3[0];
        const int i = i0 + il;
#pragma unroll
        for (int q = 0; q < 4; q++) {
            const int j = j0 + jlb + q;
            if (i > j)
                out[((size_t)(b * Nn + i)) * Nn + j] = part[q] + bias3;
        }
    }
}

// ---------------------------------------------------------------------------
// Kernel 3: per-row masked softmax (in-place on out), fills upper tri w/ -1000
// ---------------------------------------------------------------------------
__global__ void softmax_kernel(float* __restrict__ out) {
    __shared__ float red[8];
    const int row = blockIdx.x;       // b*N + i
    const int i = row % Nn;
    const int tid = threadIdx.x;      // 0..191
    float* r = out + (size_t)row * Nn;

    float x = (tid < i) ? r[tid] : (tid == i ? 0.f : -INFINITY);

    // block max
    float m = x;
#pragma unroll
    for (int off = 16; off; off >>= 1)
        m = fmaxf(m, __shfl_xor_sync(0xffffffffu, m, off));
    if ((tid & 31) == 0) red[tid >> 5] = m;
    __syncthreads();
    if (tid < 8) {
        float mm = (tid < 6) ? red[tid] : -INFINITY;
#pragma unroll
        for (int off = 4; off; off >>= 1)
            mm = fmaxf(mm, __shfl_xor_sync(0xffu, mm, off));
        if (tid == 0) red[0] = mm;
    }
    __syncthreads();
    const float bm = red[0];
    __syncthreads();

    float e = (tid <= i) ? __expf(x - bm) : 0.f;
    float s = e;
#pragma unroll
    for (int off = 16; off; off >>= 1)
        s += __shfl_xor_sync(0xffffffffu, s, off);
    if ((tid & 31) == 0) red[tid >> 5] = s;
    __syncthreads();
    if (tid < 8) {
        float ss = (tid < 6) ? red[tid] : 0.f;
#pragma unroll
        for (int off = 4; off; off >>= 1)
            ss += __shfl_xor_sync(0xffu, ss, off);
        if (tid == 0) red[0] = ss;
    }
    __syncthreads();
    const float invZ = 1.f / red[0];

    r[tid] = (tid <= i) ? e * invZ : -1000.0f;
}

// ---------------------------------------------------------------------------
extern "C" void kernel_launch(void* const* d_in, const int* in_sizes, int n_in,
                              void* d_out, int out_size) {
    const float* E  = (const float*)d_in[0];
    const float* W1 = (const float*)d_in[1];
    const float* b1 = (const float*)d_in[2];
    const float* W2 = (const float*)d_in[3];
    const float* b2 = (const float*)d_in[4];
    const float* W3 = (const float*)d_in[5];
    const float* b3 = (const float*)d_in[6];
    float* out = (float*)d_out;

    // pair_kernel smem: Wd(5120 f) + Ps2(4224 f) + Hs(9600 f)
    const int smem_bytes = (5120 + 4224 + 64 * HSB) * (int)sizeof(float);
    cudaFuncSetAttribute(pair_kernel,
                         cudaFuncAttributeMaxDynamicSharedMemorySize, smem_bytes);

    dim3 blk(16, 16);
    precompute_kernel<<<dim3(Bn * Nn / 16, 5, 2), blk>>>(E, W1, b1);

    const int n_tiles = (Nn / 8) * (Nn / 8 + 1) / 2; // 300
    pair_kernel<<<dim3(n_tiles, Bn), blk, smem_bytes>>>(E, W1, W2, b2, W3, b3, out);

    softmax_kernel<<<Bn * Nn, Nn>>>(out);
}

// round 14
// speedup vs baseline: 3.7623x; 3.7321x over previous
#include <cuda_runtime.h>
#include <cuda_bf16.h>
#include <math.h>
#include <stdint.h>

#define Bn 8
#define Nn 192
#define Dn 768
#define Hn 150

typedef unsigned int u32;
typedef unsigned long long u64;

// ---------------- device scratch ----------------
__device__ float g_A[Bn * Nn * Hn];
__device__ float g_Bm[Bn * Nn * Hn];
__device__ __align__(16) __nv_bfloat16 g_W1cbf[160 * 768];   // [n][k] = W1c[k][n], zero-pad n>=150
__device__ __align__(16) __nv_bfloat16 g_W2bf[3 * 160 * 64]; // chunk c: [n][kk] = W2[c*64+kk][n], zero-pad

// ---------------- helpers ----------------
__device__ __forceinline__ u32 s2u(const void* p) {
    u32 a; asm("{ .reg .u64 t; cvta.to.shared.u64 t, %1; cvt.u32.u64 %0, t; }" : "=r"(a) : "l"(p));
    return a;
}
__device__ __forceinline__ u32 sw128(u32 o) { return o ^ ((o >> 3) & 0x70); }
__device__ __forceinline__ u32 bf2(float lo, float hi) {  // mem order: [lo][hi]
    u32 r; asm("cvt.rn.bf16x2.f32 %0, %1, %2;" : "=r"(r) : "f"(hi), "f"(lo)); return r;
}
__device__ __forceinline__ void ldsm4(u32* r, u32 addr) {
    asm volatile("ldmatrix.sync.aligned.m8n8.x4.shared.b16 {%0,%1,%2,%3}, [%4];"
                 : "=r"(r[0]), "=r"(r[1]), "=r"(r[2]), "=r"(r[3]) : "r"(addr));
}
__device__ __forceinline__ void mma_bf16(float* c, const u32* a, u32 b0, u32 b1) {
    asm volatile(
        "mma.sync.aligned.m16n8k16.row.col.f32.bf16.bf16.f32 "
        "{%0,%1,%2,%3}, {%4,%5,%6,%7}, {%8,%9}, {%0,%1,%2,%3};"
        : "+f"(c[0]), "+f"(c[1]), "+f"(c[2]), "+f"(c[3])
        : "r"(a[0]), "r"(a[1]), "r"(a[2]), "r"(a[3]), "r"(b0), "r"(b1));
}

// ---------------------------------------------------------------------------
// Kernel 1: per-token projections A = E@W1a + b1, Bm = E@W1b.
// ---------------------------------------------------------------------------
__global__ void precompute_kernel(const float* __restrict__ E,
                                  const float* __restrict__ W1,
                                  const float* __restrict__ b1) {
    __shared__ float Es[32 * 33];
    __shared__ __align__(8) float Ws[32 * 34];
    const int hg = threadIdx.x;        // 0..7
    const int rg = threadIdx.y;        // 0..31
    const int tid = rg * 8 + hg;
    const int row0 = blockIdx.x * 32;
    const int h0 = blockIdx.y * 32;
    const int mat = blockIdx.z;
    const float* W = W1 + (size_t)mat * Dn * Hn;
    float* outp = mat ? g_Bm : g_A;

    float a0 = 0.f, a1 = 0.f, a2 = 0.f, a3 = 0.f;
    for (int kc = 0; kc < Dn; kc += 32) {
#pragma unroll
        for (int e = 0; e < 4; e++) {
            int l = e * 256 + tid; int r = l >> 5, k = l & 31;
            Es[r * 33 + k] = E[(size_t)(row0 + r) * Dn + kc + k];
        }
#pragma unroll
        for (int e = 0; e < 4; e++) {
            int l = e * 256 + tid; int k = l >> 5, hh = l & 31;
            int h = h0 + hh;
            Ws[k * 34 + hh] = (h < Hn) ? W[(size_t)(kc + k) * Hn + h] : 0.f;
        }
        __syncthreads();
#pragma unroll 8
        for (int k = 0; k < 32; k++) {
            float e = Es[rg * 33 + k];
            const float2* wr = (const float2*)(Ws + k * 34);
            float2 w0 = wr[hg], w1 = wr[hg + 8];
            a0 += e * w0.x; a1 += e * w0.y; a2 += e * w1.x; a3 += e * w1.y;
        }
        __syncthreads();
    }
    const int row = row0 + rg;
    const int ha = h0 + 2 * hg, hb = ha + 16;
    if (ha < Hn)     outp[(size_t)row * Hn + ha]     = a0 + (mat ? 0.f : b1[ha]);
    if (ha + 1 < Hn) outp[(size_t)row * Hn + ha + 1] = a1 + (mat ? 0.f : b1[ha + 1]);
    if (hb < Hn)     outp[(size_t)row * Hn + hb]     = a2 + (mat ? 0.f : b1[hb]);
    if (hb + 1 < Hn) outp[(size_t)row * Hn + hb + 1] = a3 + (mat ? 0.f : b1[hb + 1]);
}

// ---------------------------------------------------------------------------
// Kernel 1b: one-time bf16 weight conversion (W1c^T and W2^T, zero-padded).
// ---------------------------------------------------------------------------
__global__ void wconvert_kernel(const float* __restrict__ W1,
                                const float* __restrict__ W2) {
    int idx = blockIdx.x * 256 + threadIdx.x;
    if (idx < 160 * 768) {
        int n = idx / 768, k = idx - n * 768;
        float v = (n < Hn) ? W1[(size_t)(2 * Dn + k) * Hn + n] : 0.f;
        g_W1cbf[idx] = __float2bfloat16(v);
    } else {
        int r = idx - 160 * 768;
        if (r < 3 * 160 * 64) {
            int c = r / (160 * 64); int rem = r - c * (160 * 64);
            int n = rem / 64; int kk = rem - n * 64; int kg = c * 64 + kk;
            float v = (n < Hn && kg < Hn) ? W2[(size_t)kg * Hn + n] : 0.f;
            g_W2bf[r] = __float2bfloat16(v);
        }
    }
}

// ---------------------------------------------------------------------------
// Kernel 2: fused pair MLP via warp-level bf16 mma.sync (m16n8k16).
// Block = 128 pairs (8 i x 16 j), 8 warps; warp w owns pair rows 16w..16w+15.
// Layer1: K=768 in 12 chunks of 64 (P built bf16 in smem, W1c^T staged).
// Layer2: Hs bf16 in smem (stride 384B, swizzled) x W2^T in 3 K-chunks.
// ---------------------------------------------------------------------------
#define SM_P    0         // 128 x 128B  (16384)
#define SM_W    16384     // 160 x 128B  (20480)
#define SM_HS   36864     // 128 x 384B  (49152)
#define SM_EST  86016     // 24 x 66 f32 (6336)
#define SM_ABJ  92352     // 24 x 160 f32 (15360)
#define SM_BW   107712    // sb2[160] + sW3[160] f32 (1280)
#define SM_TOT  108992

__global__ __launch_bounds__(256) void pair_mma_kernel(
    const float* __restrict__ E, const float* __restrict__ b2v,
    const float* __restrict__ W3, const float* __restrict__ b3,
    float* __restrict__ out) {
    extern __shared__ __align__(1024) char smem[];
    const u32 sb = s2u(smem);
    const int tid = threadIdx.x;
    const int warp = tid >> 5;
    const int lane = tid & 31;

    // tile decode: tiles (bi, bj) with bi >= 2*bj  (156 tiles cover lower tri)
    int t = blockIdx.x, bj = 0;
#pragma unroll 1
    for (; bj < 12; bj++) { int cnt = 24 - 2 * bj; if (t < cnt) break; t -= cnt; }
    const int bi = 2 * bj + t;
    const int i0 = bi * 8, j0 = bj * 16;
    const int b = blockIdx.y;

    float* EST = (float*)(smem + SM_EST);
    float* ABJ = (float*)(smem + SM_ABJ);
    float* sb2 = (float*)(smem + SM_BW);
    float* sW3 = sb2 + 160;

    // stage per-token rows A_i (8) + B_j (16), stride 160, zero-pad h>=150
    for (int it = 0; it < 15; it++) {
        int l = it * 256 + tid;                     // < 3840
        int r = l / 160, h = l - r * 160;
        float v = 0.f;
        if (h < Hn)
            v = (r < 8) ? g_A[(size_t)(b * Nn + i0 + r) * Hn + h]
                        : g_Bm[(size_t)(b * Nn + j0 + r - 8) * Hn + h];
        ABJ[l] = v;
    }
    // stage b2 (sb2[0..159]) and W3 (sb2[160..319] = sW3), zero-pad c>=150
    for (int l = tid; l < 320; l += 256) {
        int c = (l < 160) ? l : l - 160;
        sb2[l] = (c < Hn) ? ((l < 160) ? b2v[c] : W3[c]) : 0.f;
    }

    // per-lane fragment address components
    const int m0 = warp * 16;
    const int lrow = (lane & 7) + ((lane >> 3) & 1) * 8;  // A-row add
    const int akoff2 = ((lane >> 4) & 1) * 16;            // A k byte off
    const int arow = m0 + lrow;
    const u32 aswz = (u32)((arow & 7) * 16);
    const int brow_off = (lane & 7) + ((lane >> 4) & 1) * 8;  // B-row add (per ntp)
    const int bkoff2 = ((lane >> 3) & 1) * 16;            // B k byte off

    const int pb = tid >> 1, kh = tid & 1;
    const int ilb = pb >> 4, jlb = pb & 15;

    float acc[20][4];
#pragma unroll
    for (int nt = 0; nt < 20; nt++)
#pragma unroll
        for (int q = 0; q < 4; q++) acc[nt][q] = 0.f;

    // ---- Layer 1: 12 chunks of K=64 ----
#pragma unroll 1
    for (int c = 0; c < 12; c++) {
        // stage E rows (24 x 64 f32)
#pragma unroll
        for (int e = 0; e < 6; e++) {
            int l = e * 256 + tid;
            int r = l >> 6, k = l & 63;
            int row = (r < 8) ? (i0 + r) : (j0 + r - 8);
            EST[r * 66 + k] = E[(size_t)(b * Nn + row) * Dn + c * 64 + k];
        }
        __syncthreads();
        // build P chunk (128 x 64 bf16, sw128) ; stage W1c chunk (160 x 64 bf16, sw128)
        {
            const float* ei = EST + ilb * 66;
            const float* ej = EST + (8 + jlb) * 66;
#pragma unroll
            for (int kk = 0; kk < 16; kk++) {
                int k = kh * 32 + kk * 2;
                float2 e2 = *(const float2*)(ei + k);
                float2 j2 = *(const float2*)(ej + k);
                *(u32*)(smem + SM_P + sw128((u32)(pb * 128 + k * 2))) =
                    bf2(e2.x * j2.x, e2.y * j2.y);
            }
#pragma unroll
            for (int e = 0; e < 5; e++) {
                int u2 = e * 256 + tid;              // < 1280
                int r = u2 >> 3, seg = u2 & 7;
                uint4 v = *(const uint4*)(g_W1cbf + r * 768 + c * 64 + seg * 8);
                *(uint4*)(smem + SM_W + sw128((u32)(r * 128 + seg * 16))) = v;
            }
        }
        __syncthreads();
        // MMA: 4 k-steps x 20 n-tiles
        {
            u32 a[4][4];
#pragma unroll
            for (int ks = 0; ks < 4; ks++)
                ldsm4(a[ks], sb + SM_P + (u32)arow * 128 + (((u32)(ks * 32 + akoff2)) ^ aswz));
#pragma unroll
            for (int ntp = 0; ntp < 10; ntp++) {
                int brow = ntp * 16 + brow_off;
                u32 bbase = sb + SM_W + (u32)brow * 128;
                u32 bswz = (u32)((brow & 7) * 16);
#pragma unroll
                for (int ks = 0; ks < 4; ks++) {
                    u32 bf[4];
                    ldsm4(bf, bbase + (((u32)(ks * 32 + bkoff2)) ^ bswz));
                    mma_bf16(acc[ntp * 2],     a[ks], bf[0], bf[1]);
                    mma_bf16(acc[ntp * 2 + 1], a[ks], bf[2], bf[3]);
                }
            }
        }
        __syncthreads();
    }

    // ---- Epilogue 1: + A_i + B_j, ReLU, bf16 -> Hs (stride 384B, swizzled) ----
    {
        const int gid = lane >> 2, tid4 = lane & 3;
        const int p0r = m0 + gid, p1r = p0r + 8;
        const float* Ar0 = ABJ + (p0r >> 4) * 160;
        const float* Br0 = ABJ + (8 + (p0r & 15)) * 160;
        const float* Ar1 = ABJ + (p1r >> 4) * 160;
        const float* Br1 = ABJ + (8 + (p1r & 15)) * 160;
        const u32 swz0 = (u32)((p0r & 7) * 16), swz1 = (u32)((p1r & 7) * 16);
#pragma unroll
        for (int nt = 0; nt < 20; nt++) {
            int col = nt * 8 + tid4 * 2;
            float h00 = fmaxf(acc[nt][0] + Ar0[col]     + Br0[col],     0.f);
            float h01 = fmaxf(acc[nt][1] + Ar0[col + 1] + Br0[col + 1], 0.f);
            float h10 = fmaxf(acc[nt][2] + Ar1[col]     + Br1[col],     0.f);
            float h11 = fmaxf(acc[nt][3] + Ar1[col + 1] + Br1[col + 1], 0.f);
            *(u32*)(smem + SM_HS + p0r * 384 + (((u32)(col * 2)) ^ swz0)) = bf2(h00, h01);
            *(u32*)(smem + SM_HS + p1r * 384 + (((u32)(col * 2)) ^ swz1)) = bf2(h10, h11);
            acc[nt][0] = acc[nt][1] = acc[nt][2] = acc[nt][3] = 0.f;
        }
    }
    __syncthreads();

    // ---- Layer 2: K=160 in 3 W2 chunks (4+4+2 k-steps) ----
#pragma unroll 1
    for (int c2 = 0; c2 < 3; c2++) {
#pragma unroll
        for (int e = 0; e < 5; e++) {
            int u2 = e * 256 + tid;
            int r = u2 >> 3, seg = u2 & 7;
            uint4 v = *(const uint4*)(g_W2bf + c2 * 10240 + r * 64 + seg * 8);
            *(uint4*)(smem + SM_W + sw128((u32)(r * 128 + seg * 16))) = v;
        }
        __syncthreads();
        const int nks = (c2 < 2) ? 4 : 2;
        u32 a[4][4];
        for (int ks = 0; ks < nks; ks++)
            ldsm4(a[ks], sb + SM_HS + (u32)arow * 384 +
                         (((u32)(c2 * 128 + ks * 32 + akoff2)) ^ aswz));
#pragma unroll
        for (int ntp = 0; ntp < 10; ntp++) {
            int brow = ntp * 16 + brow_off;
            u32 bbase = sb + SM_W + (u32)brow * 128;
            u32 bswz = (u32)((brow & 7) * 16);
            for (int ks = 0; ks < nks; ks++) {
                u32 bf[4];
                ldsm4(bf, bbase + (((u32)(ks * 32 + bkoff2)) ^ bswz));
                mma_bf16(acc[ntp * 2],     a[ks], bf[0], bf[1]);
                mma_bf16(acc[ntp * 2 + 1], a[ks], bf[2], bf[3]);
            }
        }
        __syncthreads();
    }

    // ---- Epilogue 2: relu(D2 + b2) @ W3, reduce over tid4 group, scatter ----
    {
        const int gid = lane >> 2, tid4 = lane & 3;
        float s0 = 0.f, s1 = 0.f;
#pragma unroll
        for (int nt = 0; nt < 20; nt++) {
            int col = nt * 8 + tid4 * 2;
            s0 += fmaxf(acc[nt][0] + sb2[col],     0.f) * sW3[col];
            s0 += fmaxf(acc[nt][1] + sb2[col + 1], 0.f) * sW3[col + 1];
            s1 += fmaxf(acc[nt][2] + sb2[col],     0.f) * sW3[col];
            s1 += fmaxf(acc[nt][3] + sb2[col + 1], 0.f) * sW3[col + 1];
        }
        s0 += __shfl_xor_sync(0xffffffffu, s0, 1);
        s0 += __shfl_xor_sync(0xffffffffu, s0, 2);
        s1 += __shfl_xor_sync(0xffffffffu, s1, 1);
        s1 += __shfl_xor_sync(0xffffffffu, s1, 2);
        if (tid4 == 0) {
            const float bias3 = b3[0];
            int p0r = m0 + gid;
            int gi = i0 + (p0r >> 4), gj = j0 + (p0r & 15);
            if (gi > gj) out[(size_t)(b * Nn + gi) * Nn + gj] = s0 + bias3;
            int p1r = p0r + 8;
            gi = i0 + (p1r >> 4); gj = j0 + (p1r & 15);
            if (gi > gj) out[(size_t)(b * Nn + gi) * Nn + gj] = s1 + bias3;
        }
    }
}

// ---------------------------------------------------------------------------
// Kernel 3: per-row masked softmax (in-place), fills upper tri with -1000
// ---------------------------------------------------------------------------
__global__ void softmax_kernel(float* __restrict__ out) {
    __shared__ float red[8];
    const int row = blockIdx.x;
    const int i = row % Nn;
    const int tid = threadIdx.x;
    float* r = out + (size_t)row * Nn;

    float x = (tid < i) ? r[tid] : (tid == i ? 0.f : -INFINITY);
    float m = x;
#pragma unroll
    for (int off = 16; off; off >>= 1)
        m = fmaxf(m, __shfl_xor_sync(0xffffffffu, m, off));
    if ((tid & 31) == 0) red[tid >> 5] = m;
    __syncthreads();
    if (tid < 8) {
        float mm = (tid < 6) ? red[tid] : -INFINITY;
#pragma unroll
        for (int off = 4; off; off >>= 1)
            mm = fmaxf(mm, __shfl_xor_sync(0xffu, mm, off));
        if (tid == 0) red[0] = mm;
    }
    __syncthreads();
    const float bm = red[0];
    __syncthreads();
    float e = (tid <= i) ? __expf(x - bm) : 0.f;
    float s = e;
#pragma unroll
    for (int off = 16; off; off >>= 1)
        s += __shfl_xor_sync(0xffffffffu, s, off);
    if ((tid & 31) == 0) red[tid >> 5] = s;
    __syncthreads();
    if (tid < 8) {
        float ss = (tid < 6) ? red[tid] : 0.f;
#pragma unroll
        for (int off = 4; off; off >>= 1)
            ss += __shfl_xor_sync(0xffu, ss, off);
        if (tid == 0) red[0] = ss;
    }
    __syncthreads();
    const float invZ = 1.f / red[0];
    r[tid] = (tid <= i) ? e * invZ : -1000.0f;
}

// ---------------------------------------------------------------------------
extern "C" void kernel_launch(void* const* d_in, const int* in_sizes, int n_in,
                              void* d_out, int out_size) {
    const float* E  = (const float*)d_in[0];
    const float* W1 = (const float*)d_in[1];
    const float* b1 = (const float*)d_in[2];
    const float* W2 = (const float*)d_in[3];
    const float* b2 = (const float*)d_in[4];
    const float* W3 = (const float*)d_in[5];
    const float* b3 = (const float*)d_in[6];
    float* out = (float*)d_out;

    cudaFuncSetAttribute(pair_mma_kernel,
                         cudaFuncAttributeMaxDynamicSharedMemorySize, SM_TOT);

    precompute_kernel<<<dim3(48, 5, 2), dim3(8, 32)>>>(E, W1, b1);
    wconvert_kernel<<<600, 256>>>(W1, W2);
    pair_mma_kernel<<<dim3(156, Bn), 256, SM_TOT>>>(E, b2, W3, b3, out);
    softmax_kernel<<<Bn * Nn, Nn>>>(out);
}

// round 15
// speedup vs baseline: 4.2837x; 1.1386x over previous
#include <cuda_runtime.h>
#include <cuda_bf16.h>
#include <math.h>
#include <stdint.h>

#define Bn 8
#define Nn 192
#define Dn 768
#define Hn 150

typedef unsigned int u32;
typedef unsigned long long u64;

// ---------------- device scratch ----------------
__device__ float g_A[Bn * Nn * Hn];
__device__ float g_Bm[Bn * Nn * Hn];
__device__ __align__(16) __nv_bfloat16 g_Ebf[Bn * Nn * Dn];  // bf16 copy of E
__device__ __align__(16) __nv_bfloat16 g_W1cbf[160 * 768];   // [n][k] = W1c[k][n], zero-pad n>=150
__device__ __align__(16) __nv_bfloat16 g_W2bf[3 * 160 * 64]; // chunk c: [n][kk] = W2[c*64+kk][n], zero-pad

// ---------------- helpers ----------------
__device__ __forceinline__ u32 s2u(const void* p) {
    u32 a; asm("{ .reg .u64 t; cvta.to.shared.u64 t, %1; cvt.u32.u64 %0, t; }" : "=r"(a) : "l"(p));
    return a;
}
__device__ __forceinline__ u32 sw128(u32 o) { return o ^ ((o >> 3) & 0x70); }
__device__ __forceinline__ u32 bf2(float lo, float hi) {  // mem order: [lo][hi]
    u32 r; asm("cvt.rn.bf16x2.f32 %0, %1, %2;" : "=r"(r) : "f"(hi), "f"(lo)); return r;
}
__device__ __forceinline__ void ldsm4(u32* r, u32 addr) {
    asm volatile("ldmatrix.sync.aligned.m8n8.x4.shared.b16 {%0,%1,%2,%3}, [%4];"
                 : "=r"(r[0]), "=r"(r[1]), "=r"(r[2]), "=r"(r[3]) : "r"(addr));
}
__device__ __forceinline__ void mma_bf16(float* c, const u32* a, u32 b0, u32 b1) {
    asm volatile(
        "mma.sync.aligned.m16n8k16.row.col.f32.bf16.bf16.f32 "
        "{%0,%1,%2,%3}, {%4,%5,%6,%7}, {%8,%9}, {%0,%1,%2,%3};"
        : "+f"(c[0]), "+f"(c[1]), "+f"(c[2]), "+f"(c[3])
        : "r"(a[0]), "r"(a[1]), "r"(a[2]), "r"(a[3]), "r"(b0), "r"(b1));
}

// ---------------------------------------------------------------------------
// Kernel 1: per-token projections A = E@W1a + b1, Bm = E@W1b.
// Grid (12, 5, 2). Block 256: thread = 4 rows x 4 contiguous h. 128 rows x 32 h.
// ---------------------------------------------------------------------------
__global__ void precompute_kernel(const float* __restrict__ E,
                                  const float* __restrict__ W1,
                                  const float* __restrict__ b1) {
    __shared__ __align__(16) float Es[128 * 33];
    __shared__ __align__(16) float Ws[32 * 36];
    const int tid = threadIdx.x;
    const int hq = tid & 7;            // 8 h-groups x 4 h
    const int rq = tid >> 3;           // 32 row-groups
    const int row0 = blockIdx.x * 128;
    const int h0 = blockIdx.y * 32;
    const int mat = blockIdx.z;
    const float* W = W1 + (size_t)mat * Dn * Hn;
    float* outp = mat ? g_Bm : g_A;

    float acc[4][4];
#pragma unroll
    for (int rr = 0; rr < 4; rr++)
#pragma unroll
        for (int hh = 0; hh < 4; hh++) acc[rr][hh] = 0.f;

    for (int kc = 0; kc < Dn; kc += 32) {
#pragma unroll
        for (int e = 0; e < 16; e++) {
            int l = e * 256 + tid;      // < 4096
            int r = l >> 5, k = l & 31;
            Es[r * 33 + k] = E[(size_t)(row0 + r) * Dn + kc + k];
        }
#pragma unroll
        for (int e = 0; e < 4; e++) {
            int l = e * 256 + tid;      // < 1024
            int k = l >> 5, hh = l & 31;
            int h = h0 + hh;
            Ws[k * 36 + hh] = (h < Hn) ? W[(size_t)(kc + k) * Hn + h] : 0.f;
        }
        __syncthreads();
#pragma unroll 4
        for (int k = 0; k < 32; k++) {
            float4 w4 = *(const float4*)(Ws + k * 36 + hq * 4);
#pragma unroll
            for (int rr = 0; rr < 4; rr++) {
                float e = Es[(rq + 32 * rr) * 33 + k];
                acc[rr][0] += e * w4.x; acc[rr][1] += e * w4.y;
                acc[rr][2] += e * w4.z; acc[rr][3] += e * w4.w;
            }
        }
        __syncthreads();
    }
#pragma unroll
    for (int rr = 0; rr < 4; rr++) {
        int row = row0 + rq + 32 * rr;
#pragma unroll
        for (int hh = 0; hh < 4; hh++) {
            int h = h0 + hq * 4 + hh;
            if (h < Hn)
                outp[(size_t)row * Hn + h] = acc[rr][hh] + (mat ? 0.f : b1[h]);
        }
    }
}

// ---------------------------------------------------------------------------
// Kernel 1b: one-time bf16 conversion: E, W1c^T, W2^T (zero-padded).
// ---------------------------------------------------------------------------
#define NE (Bn * Nn * Dn)             // 1179648
__global__ void wconvert_kernel(const float* __restrict__ E,
                                const float* __restrict__ W1,
                                const float* __restrict__ W2) {
    int idx = blockIdx.x * 256 + threadIdx.x;
    if (idx < NE) {
        g_Ebf[idx] = __float2bfloat16(E[idx]);
    } else {
        int q = idx - NE;
        if (q < 160 * 768) {
            int n = q / 768, k = q - n * 768;
            float v = (n < Hn) ? W1[(size_t)(2 * Dn + k) * Hn + n] : 0.f;
            g_W1cbf[q] = __float2bfloat16(v);
        } else {
            int r = q - 160 * 768;
            if (r < 3 * 160 * 64) {
                int c = r / (160 * 64); int rem = r - c * (160 * 64);
                int n = rem / 64; int kk = rem - n * 64; int kg = c * 64 + kk;
                float v = (n < Hn && kg < Hn) ? W2[(size_t)kg * Hn + n] : 0.f;
                g_W2bf[r] = __float2bfloat16(v);
            }
        }
    }
}

// ---------------------------------------------------------------------------
// Kernel 2: fused pair MLP via warp-level bf16 mma.sync (m16n8k16).
// Block = 128 pairs (8 i x 16 j), 8 warps; warp w owns pair rows 16w..16w+15.
// Layer1: K=768 in 12 chunks of 64; P built via mul.bf16x2 from bf16 E.
// Layer2: Hs bf16 in smem (stride 384B, swizzled) x W2^T in 3 K-chunks.
// ---------------------------------------------------------------------------
#define SM_P    0         // 128 x 128B  (16384)
#define SM_W    16384     // 160 x 128B  (20480)
#define SM_HS   36864     // 128 x 384B  (49152)
#define SM_EST  86016     // 24 x 33 u32 (3168)
#define SM_ABJ  89184     // 24 x 160 f32 (15360)
#define SM_BW   104544    // sb2[160] + sW3[160] f32 (1280)
#define SM_TOT  105984

__global__ __launch_bounds__(256) void pair_mma_kernel(
    const float* __restrict__ b2v,
    const float* __restrict__ W3, const float* __restrict__ b3,
    float* __restrict__ out) {
    extern __shared__ __align__(1024) char smem[];
    const u32 sb = s2u(smem);
    const int tid = threadIdx.x;
    const int warp = tid >> 5;
    const int lane = tid & 31;

    // tile decode: tiles (bi, bj) with bi >= 2*bj  (156 tiles cover lower tri)
    int t = blockIdx.x, bj = 0;
#pragma unroll 1
    for (; bj < 12; bj++) { int cnt = 24 - 2 * bj; if (t < cnt) break; t -= cnt; }
    const int bi = 2 * bj + t;
    const int i0 = bi * 8, j0 = bj * 16;
    const int b = blockIdx.y;

    u32* ESTu = (u32*)(smem + SM_EST);
    float* ABJ = (float*)(smem + SM_ABJ);
    float* sb2 = (float*)(smem + SM_BW);
    float* sW3 = sb2 + 160;

    // stage per-token rows A_i (8) + B_j (16), stride 160, zero-pad h>=150
    for (int it = 0; it < 15; it++) {
        int l = it * 256 + tid;                     // < 3840
        int r = l / 160, h = l - r * 160;
        float v = 0.f;
        if (h < Hn)
            v = (r < 8) ? g_A[(size_t)(b * Nn + i0 + r) * Hn + h]
                        : g_Bm[(size_t)(b * Nn + j0 + r - 8) * Hn + h];
        ABJ[l] = v;
    }
    // stage b2 (sb2[0..159]) and W3 (sb2[160..319] = sW3), zero-pad c>=150
    for (int l = tid; l < 320; l += 256) {
        int c = (l < 160) ? l : l - 160;
        sb2[l] = (c < Hn) ? ((l < 160) ? b2v[c] : W3[c]) : 0.f;
    }

    // per-lane fragment address components
    const int m0 = warp * 16;
    const int lrow = (lane & 7) + ((lane >> 3) & 1) * 8;  // A-row add
    const int akoff2 = ((lane >> 4) & 1) * 16;            // A k byte off
    const int arow = m0 + lrow;
    const u32 aswz = (u32)((arow & 7) * 16);
    const int brow_off = (lane & 7) + ((lane >> 4) & 1) * 8;  // B-row add (per ntp)
    const int bkoff2 = ((lane >> 3) & 1) * 16;            // B k byte off

    const int pb = tid >> 1, kh = tid & 1;
    const int ilb = pb >> 4, jlb = pb & 15;

    float acc[20][4];
#pragma unroll
    for (int nt = 0; nt < 20; nt++)
#pragma unroll
        for (int q = 0; q < 4; q++) acc[nt][q] = 0.f;

    // ---- Layer 1: 12 chunks of K=64 ----
#pragma unroll 1
    for (int c = 0; c < 12; c++) {
        // stage bf16 E rows (24 rows x 32 u32), stride 33 u32
#pragma unroll
        for (int e = 0; e < 3; e++) {
            int l = e * 256 + tid;                   // < 768
            int r = l >> 5, kk = l & 31;
            int row = (r < 8) ? (i0 + r) : (j0 + r - 8);
            ESTu[r * 33 + kk] =
                *(const u32*)(g_Ebf + (size_t)(b * Nn + row) * Dn + c * 64 + kk * 2);
        }
        __syncthreads();
        // build P chunk (128 x 64 bf16, sw128) via mul.bf16x2
        {
            const u32* eiu = ESTu + ilb * 33 + kh * 16;
            const u32* eju = ESTu + (8 + jlb) * 33 + kh * 16;
#pragma unroll
            for (int kk = 0; kk < 16; kk++) {
                u32 p;
                asm("mul.bf16x2 %0, %1, %2;" : "=r"(p) : "r"(eiu[kk]), "r"(eju[kk]));
                *(u32*)(smem + SM_P + sw128((u32)(pb * 128 + kh * 64 + kk * 4))) = p;
            }
        }
        // stage W1c chunk (160 x 64 bf16, sw128)
        {
#pragma unroll
            for (int e = 0; e < 5; e++) {
                int u2 = e * 256 + tid;              // < 1280
                int r = u2 >> 3, seg = u2 & 7;
                uint4 v = *(const uint4*)(g_W1cbf + r * 768 + c * 64 + seg * 8);
                *(uint4*)(smem + SM_W + sw128((u32)(r * 128 + seg * 16))) = v;
            }
        }
        __syncthreads();
        // MMA: 4 k-steps x 20 n-tiles
        {
            u32 a[4][4];
#pragma unroll
            for (int ks = 0; ks < 4; ks++)
                ldsm4(a[ks], sb + SM_P + (u32)arow * 128 + (((u32)(ks * 32 + akoff2)) ^ aswz));
#pragma unroll
            for (int ntp = 0; ntp < 10; ntp++) {
                int brow = ntp * 16 + brow_off;
                u32 bbase = sb + SM_W + (u32)brow * 128;
                u32 bswz = (u32)((brow & 7) * 16);
#pragma unroll
                for (int ks = 0; ks < 4; ks++) {
                    u32 bf[4];
                    ldsm4(bf, bbase + (((u32)(ks * 32 + bkoff2)) ^ bswz));
                    mma_bf16(acc[ntp * 2],     a[ks], bf[0], bf[1]);
                    mma_bf16(acc[ntp * 2 + 1], a[ks], bf[2], bf[3]);
                }
            }
        }
        __syncthreads();
    }

    // ---- Epilogue 1: + A_i + B_j, ReLU, bf16 -> Hs (stride 384B, swizzled) ----
    {
        const int gid = lane >> 2, tid4 = lane & 3;
        const int p0r = m0 + gid, p1r = p0r + 8;
        const float* Ar0 = ABJ + (p0r >> 4) * 160;
        const float* Br0 = ABJ + (8 + (p0r & 15)) * 160;
        const float* Ar1 = ABJ + (p1r >> 4) * 160;
        const float* Br1 = ABJ + (8 + (p1r & 15)) * 160;
        const u32 swz0 = (u32)((p0r & 7) * 16), swz1 = (u32)((p1r & 7) * 16);
#pragma unroll
        for (int nt = 0; nt < 20; nt++) {
            int col = nt * 8 + tid4 * 2;
            float h00 = fmaxf(acc[nt][0] + Ar0[col]     + Br0[col],     0.f);
            float h01 = fmaxf(acc[nt][1] + Ar0[col + 1] + Br0[col + 1], 0.f);
            float h10 = fmaxf(acc[nt][2] + Ar1[col]     + Br1[col],     0.f);
            float h11 = fmaxf(acc[nt][3] + Ar1[col + 1] + Br1[col + 1], 0.f);
            *(u32*)(smem + SM_HS + p0r * 384 + (((u32)(col * 2)) ^ swz0)) = bf2(h00, h01);
            *(u32*)(smem + SM_HS + p1r * 384 + (((u32)(col * 2)) ^ swz1)) = bf2(h10, h11);
            acc[nt][0] = acc[nt][1] = acc[nt][2] = acc[nt][3] = 0.f;
        }
    }
    __syncthreads();

    // ---- Layer 2: K=160 in 3 W2 chunks (4+4+2 k-steps) ----
#pragma unroll 1
    for (int c2 = 0; c2 < 3; c2++) {
#pragma unroll
        for (int e = 0; e < 5; e++) {
            int u2 = e * 256 + tid;
            int r = u2 >> 3, seg = u2 & 7;
            uint4 v = *(const uint4*)(g_W2bf + c2 * 10240 + r * 64 + seg * 8);
            *(uint4*)(smem + SM_W + sw128((u32)(r * 128 + seg * 16))) = v;
        }
        __syncthreads();
        const int nks = (c2 < 2) ? 4 : 2;
        u32 a[4][4];
        for (int ks = 0; ks < nks; ks++)
            ldsm4(a[ks], sb + SM_HS + (u32)arow * 384 +
                         (((u32)(c2 * 128 + ks * 32 + akoff2)) ^ aswz));
#pragma unroll
        for (int ntp = 0; ntp < 10; ntp++) {
            int brow = ntp * 16 + brow_off;
            u32 bbase = sb + SM_W + (u32)brow * 128;
            u32 bswz = (u32)((brow & 7) * 16);
            for (int ks = 0; ks < nks; ks++) {
                u32 bf[4];
                ldsm4(bf, bbase + (((u32)(ks * 32 + bkoff2)) ^ bswz));
                mma_bf16(acc[ntp * 2],     a[ks], bf[0], bf[1]);
                mma_bf16(acc[ntp * 2 + 1], a[ks], bf[2], bf[3]);
            }
        }
        __syncthreads();
    }

    // ---- Epilogue 2: relu(D2 + b2) @ W3, reduce over tid4 group, scatter ----
    {
        const int gid = lane >> 2, tid4 = lane & 3;
        float s0 = 0.f, s1 = 0.f;
#pragma unroll
        for (int nt = 0; nt < 20; nt++) {
            int col = nt * 8 + tid4 * 2;
            s0 += fmaxf(acc[nt][0] + sb2[col],     0.f) * sW3[col];
            s0 += fmaxf(acc[nt][1] + sb2[col + 1], 0.f) * sW3[col + 1];
            s1 += fmaxf(acc[nt][2] + sb2[col],     0.f) * sW3[col];
            s1 += fmaxf(acc[nt][3] + sb2[col + 1], 0.f) * sW3[col + 1];
        }
        s0 += __shfl_xor_sync(0xffffffffu, s0, 1);
        s0 += __shfl_xor_sync(0xffffffffu, s0, 2);
        s1 += __shfl_xor_sync(0xffffffffu, s1, 1);
        s1 += __shfl_xor_sync(0xffffffffu, s1, 2);
        if (tid4 == 0) {
            const float bias3 = b3[0];
            int p0r = m0 + gid;
            int gi = i0 + (p0r >> 4), gj = j0 + (p0r & 15);
            if (gi > gj) out[(size_t)(b * Nn + gi) * Nn + gj] = s0 + bias3;
            int p1r = p0r + 8;
            gi = i0 + (p1r >> 4); gj = j0 + (p1r & 15);
            if (gi > gj) out[(size_t)(b * Nn + gi) * Nn + gj] = s1 + bias3;
        }
    }
}

// ---------------------------------------------------------------------------
// Kernel 3: per-row masked softmax (in-place), fills upper tri with -1000
// ---------------------------------------------------------------------------
__global__ void softmax_kernel(float* __restrict__ out) {
    __shared__ float red[8];
    const int row = blockIdx.x;
    const int i = row % Nn;
    const int tid = threadIdx.x;
    float* r = out + (size_t)row * Nn;

    float x = (tid < i) ? r[tid] : (tid == i ? 0.f : -INFINITY);
    float m = x;
#pragma unroll
    for (int off = 16; off; off >>= 1)
        m = fmaxf(m, __shfl_xor_sync(0xffffffffu, m, off));
    if ((tid & 31) == 0) red[tid >> 5] = m;
    __syncthreads();
    if (tid < 8) {
        float mm = (tid < 6) ? red[tid] : -INFINITY;
#pragma unroll
        for (int off = 4; off; off >>= 1)
            mm = fmaxf(mm, __shfl_xor_sync(0xffu, mm, off));
        if (tid == 0) red[0] = mm;
    }
    __syncthreads();
    const float bm = red[0];
    __syncthreads();
    float e = (tid <= i) ? __expf(x - bm) : 0.f;
    float s = e;
#pragma unroll
    for (int off = 16; off; off >>= 1)
        s += __shfl_xor_sync(0xffffffffu, s, off);
    if ((tid & 31) == 0) red[tid >> 5] = s;
    __syncthreads();
    if (tid < 8) {
        float ss = (tid < 6) ? red[tid] : 0.f;
#pragma unroll
        for (int off = 4; off; off >>= 1)
            ss += __shfl_xor_sync(0xffu, ss, off);
        if (tid == 0) red[0] = ss;
    }
    __syncthreads();
    const float invZ = 1.f / red[0];
    r[tid] = (tid <= i) ? e * invZ : -1000.0f;
}

// ---------------------------------------------------------------------------
extern "C" void kernel_launch(void* const* d_in, const int* in_sizes, int n_in,
                              void* d_out, int out_size) {
    const float* E  = (const float*)d_in[0];
    const float* W1 = (const float*)d_in[1];
    const float* b1 = (const float*)d_in[2];
    const float* W2 = (const float*)d_in[3];
    const float* b2 = (const float*)d_in[4];
    const float* W3 = (const float*)d_in[5];
    const float* b3 = (const float*)d_in[6];
    float* out = (float*)d_out;

    cudaFuncSetAttribute(pair_mma_kernel,
                         cudaFuncAttributeMaxDynamicSharedMemorySize, SM_TOT);

    precompute_kernel<<<dim3(12, 5, 2), 256>>>(E, W1, b1);
    const int nconv = (NE + 160 * 768 + 3 * 160 * 64 + 255) / 256;  // 5208
    wconvert_kernel<<<nconv, 256>>>(E, W1, W2);
    pair_mma_kernel<<<dim3(156, Bn), 256, SM_TOT>>>(b2, W3, b3, out);
    softmax_kernel<<<Bn * Nn, Nn>>>(out);
}